// round 3
// baseline (speedup 1.0000x reference)
#include <cuda_runtime.h>
#include <math.h>

#define NB 256      // batch
#define CC 256      // channels
#define TT 64       // time
#define VV 25       // vertices
#define DD 10       // final SPD dim
#define OUTD 64
#define FEATD 100

// ---------------------------------------------------------------------------
// Fully fused: per block = one sample.
//  phase 1: 8 warps stream x[n] (1.64 MB), temporal mean, project by
//           Wc = W1@W2@W3 -> smem y[256][10]
//  phase 2: warp 0 only: one-pass cov (Gram+mean, butterfly-reduced),
//           register-resident parallel Jacobi (lane i owns row i, compile-time
//           pair schedule, zero block barriers), logeig
//  phase 3: 64 threads: FC
// ---------------------------------------------------------------------------
__global__ void __launch_bounds__(256)
fused_kernel(const float* __restrict__ x,
             const float* __restrict__ W1,
             const float* __restrict__ W2,
             const float* __restrict__ W3,
             const float* __restrict__ fcw,
             const float* __restrict__ fcb,
             float* __restrict__ out) {
    __shared__ float t15[VV * 15];
    __shared__ float sWc[VV * DD + 32];   // padded: lanes 10..31 read pad
    __shared__ float sy [CC * DD];        // 10240 B
    __shared__ float sG [55];
    __shared__ float smn[DD];
    __shared__ float sV [DD * DD];
    __shared__ float sL [FEATD];

    const int tid  = threadIdx.x;
    const int n    = blockIdx.x;
    const int warp = tid >> 5;
    const int lane = tid & 31;

    // ---- Wc = (W1 @ W2) @ W3 (redundant per block, ~11K FMA) ----
    for (int e = tid; e < VV * 15; e += 256) {
        int i = e / 15, j = e % 15;
        float s = 0.f;
        #pragma unroll
        for (int k = 0; k < 20; k++) s += W1[i * 20 + k] * W2[k * 15 + j];
        t15[e] = s;
    }
    __syncthreads();
    for (int e = tid; e < VV * DD + 32; e += 256) {
        float s = 0.f;
        if (e < VV * DD) {
            int i = e / DD, j = e % DD;
            #pragma unroll
            for (int k = 0; k < 15; k++) s += t15[i * 15 + k] * W3[k * DD + j];
        }
        sWc[e] = s;
    }
    __syncthreads();

    // ---- phase 1: stream + temporal mean + project. warp w: channels
    //      [32w, 32w+32). 25 active lanes per row; row = 6400 contiguous B.
    for (int c = warp * 32; c < warp * 32 + 32; c++) {
        float xm = 0.f;
        if (lane < VV) {
            const float* p = x + ((size_t)n * CC + c) * (TT * VV) + lane;
            float a0 = 0.f, a1 = 0.f, a2 = 0.f, a3 = 0.f;
            float a4 = 0.f, a5 = 0.f, a6 = 0.f, a7 = 0.f;
            #pragma unroll
            for (int t = 0; t < TT; t += 8) {
                a0 += p[(t + 0) * VV];
                a1 += p[(t + 1) * VV];
                a2 += p[(t + 2) * VV];
                a3 += p[(t + 3) * VV];
                a4 += p[(t + 4) * VV];
                a5 += p[(t + 5) * VV];
                a6 += p[(t + 6) * VV];
                a7 += p[(t + 7) * VV];
            }
            xm = ((a0 + a1) + (a2 + a3)) + ((a4 + a5) + (a6 + a7));
            xm *= (1.0f / TT);
        }
        float y = 0.f;
        #pragma unroll
        for (int v = 0; v < VV; v++) {
            float xv = __shfl_sync(0xffffffffu, xm, v);
            y += xv * sWc[v * DD + lane];           // lanes>=10 hit pad
        }
        if (lane < DD) sy[c * DD + lane] = y;
    }
    __syncthreads();

    // ---- phase 2: warp 0 does cov + Jacobi + logeig ----
    if (warp == 0) {
        // one-pass raw Gram + sums; channels c = lane + 32*i
        float m[DD];
        float g[55];
        #pragma unroll
        for (int j = 0; j < DD; j++) m[j] = 0.f;
        #pragma unroll
        for (int k = 0; k < 55; k++) g[k] = 0.f;
        #pragma unroll
        for (int i = 0; i < 8; i++) {
            const int c = lane + i * 32;
            float yv[DD];
            #pragma unroll
            for (int j = 0; j < DD; j++) yv[j] = sy[c * DD + j];
            #pragma unroll
            for (int j = 0; j < DD; j++) m[j] += yv[j];
            int idx = 0;
            #pragma unroll
            for (int p = 0; p < DD; p++)
                #pragma unroll
                for (int q = p; q < DD; q++) g[idx++] += yv[p] * yv[q];
        }
        // butterfly reductions across the warp
        #pragma unroll
        for (int j = 0; j < DD; j++) {
            #pragma unroll
            for (int off = 16; off >= 1; off >>= 1)
                m[j] += __shfl_xor_sync(0xffffffffu, m[j], off);
        }
        #pragma unroll
        for (int k = 0; k < 55; k++) {
            #pragma unroll
            for (int off = 16; off >= 1; off >>= 1)
                g[k] += __shfl_xor_sync(0xffffffffu, g[k], off);
        }
        if (lane == 0) {
            #pragma unroll
            for (int k = 0; k < 55; k++) sG[k] = g[k];
            #pragma unroll
            for (int j = 0; j < DD; j++) smn[j] = m[j] * (1.0f / CC);
        }
        __syncwarp();

        // lane i (<10) builds row i of A; V = I. Lanes>=10 use clamped index.
        const int li = (lane < DD) ? lane : 0;
        float Ar[DD], Vr[DD];
        {
            const float mi = smn[li];
            #pragma unroll
            for (int j = 0; j < DD; j++) {
                int p = li < j ? li : j;
                int q = li < j ? j : li;
                int idx = 10 * p - (p * (p - 1)) / 2 + (q - p);
                float cov = (sG[idx] - (float)CC * mi * smn[j]) * (1.0f / (CC - 1));
                Ar[j] = cov + ((li == j) ? 1e-8f : 0.f);
                Vr[j] = (li == j) ? 1.f : 0.f;
            }
        }

        // ---- register Jacobi: 5 sweeps x 9 rounds, compile-time schedule ----
        for (int sweep = 0; sweep < 5; sweep++) {
            #pragma unroll
            for (int r = 0; r < 9; r++) {
                float cc[5], ss[5];
                float cl = 1.f, sl = 0.f;
                int partner = lane;
                #pragma unroll
                for (int k = 0; k < 5; k++) {
                    const int i1 = (k == 0) ? 0 : ((r + k - 1) % 9) + 1;
                    const int i2 = ((r + 8 - k) % 9) + 1;
                    const int p = i1 < i2 ? i1 : i2;
                    const int q = i1 < i2 ? i2 : i1;
                    float App = __shfl_sync(0xffffffffu, Ar[p], p);
                    float Aqq = __shfl_sync(0xffffffffu, Ar[q], q);
                    float Apq = __shfl_sync(0xffffffffu, Ar[q], p);
                    float c_ = 1.f, s_ = 0.f;
                    if (fabsf(Apq) > 1e-20f) {
                        float tau = (Aqq - App) / (2.f * Apq);
                        float tt  = copysignf(1.f, tau) /
                                    (fabsf(tau) + sqrtf(1.f + tau * tau));
                        c_ = rsqrtf(1.f + tt * tt);
                        s_ = tt * c_;
                    }
                    cc[k] = c_; ss[k] = s_;
                    if (lane == p) { cl = c_; sl = -s_; partner = q; }
                    if (lane == q) { cl = c_; sl =  s_; partner = p; }
                }
                // row phase: A <- J^T A  (exchange full partner row)
                float prow[DD];
                #pragma unroll
                for (int j = 0; j < DD; j++)
                    prow[j] = __shfl_sync(0xffffffffu, Ar[j], partner);
                #pragma unroll
                for (int j = 0; j < DD; j++)
                    Ar[j] = cl * Ar[j] + sl * prow[j];
                // col phase: A <- A J ; V <- V J (static indices)
                #pragma unroll
                for (int k = 0; k < 5; k++) {
                    const int i1 = (k == 0) ? 0 : ((r + k - 1) % 9) + 1;
                    const int i2 = ((r + 8 - k) % 9) + 1;
                    const int p = i1 < i2 ? i1 : i2;
                    const int q = i1 < i2 ? i2 : i1;
                    float a = Ar[p], b = Ar[q];
                    Ar[p] = cc[k] * a - ss[k] * b;
                    Ar[q] = ss[k] * a + cc[k] * b;
                    float va = Vr[p], vb = Vr[q];
                    Vr[p] = cc[k] * va - ss[k] * vb;
                    Vr[q] = ss[k] * va + cc[k] * vb;
                }
            }
        }

        // eigenvalues -> log
        float lw[DD];
        #pragma unroll
        for (int k = 0; k < DD; k++) {
            float lam = __shfl_sync(0xffffffffu, Ar[k], k);
            lw[k] = logf(fmaxf(lam, 1e-12f));
        }
        if (lane < DD) {
            #pragma unroll
            for (int j = 0; j < DD; j++) sV[lane * DD + j] = Vr[j];
        }
        __syncwarp();
        if (lane < DD) {
            #pragma unroll
            for (int j = 0; j < DD; j++) {
                float s = 0.f;
                #pragma unroll
                for (int k = 0; k < DD; k++)
                    s += Vr[k] * lw[k] * sV[j * DD + k];
                sL[lane * DD + j] = s;
            }
        }
    }
    __syncthreads();

    // ---- phase 3: FC ----
    if (tid < OUTD) {
        float s = fcb[tid];
        const float* wr = fcw + tid * FEATD;
        #pragma unroll 5
        for (int f = 0; f < FEATD; f++) s += sL[f] * wr[f];
        out[n * OUTD + tid] = s;
    }
}

// ---------------------------------------------------------------------------
extern "C" void kernel_launch(void* const* d_in, const int* in_sizes, int n_in,
                              void* d_out, int out_size) {
    const float *x = nullptr, *W1 = nullptr, *W2 = nullptr, *W3 = nullptr;
    const float *fcw = nullptr, *fcb = nullptr;
    for (int i = 0; i < n_in; i++) {
        switch (in_sizes[i]) {
            case NB * CC * TT * VV: x   = (const float*)d_in[i]; break;
            case 500:               W1  = (const float*)d_in[i]; break;
            case 300:               W2  = (const float*)d_in[i]; break;
            case 150:               W3  = (const float*)d_in[i]; break;
            case 6400:              fcw = (const float*)d_in[i]; break;
            case 64:                fcb = (const float*)d_in[i]; break;
            default: break;
        }
    }
    fused_kernel<<<NB, 256>>>(x, W1, W2, W3, fcw, fcb, (float*)d_out);
}

// round 4
// speedup vs baseline: 1.0097x; 1.0097x over previous
#include <cuda_runtime.h>
#include <math.h>

#define NB 256      // batch
#define CC 256      // channels
#define TT 64       // time
#define VV 25       // vertices
#define DD 10       // final SPD dim
#define OUTD 64
#define FEATD 100

// scratch (allocation-free rule)
__device__ float g_y[NB * CC * DD];      // projected 10-vectors, 2.6 MB (L2-resident)

// ---------------------------------------------------------------------------
// Kernel 1: per (n,c) row: temporal mean (25-dim) then project through
// Wc = W1@W2@W3 -> 10-vector. One warp per row, lean registers, high
// occupancy -> this kernel alone must pin DRAM. __ldcs: single-use stream.
// ---------------------------------------------------------------------------
__global__ void __launch_bounds__(256)
meanproj_kernel(const float* __restrict__ x,
                const float* __restrict__ W1,
                const float* __restrict__ W2,
                const float* __restrict__ W3) {
    __shared__ float t15[VV * 15];
    __shared__ float sWc[VV * DD + 32];   // padded so lanes>=10 read safely

    const int tid = threadIdx.x;

    // Wc = (W1 @ W2) @ W3 in smem (redundant per block, negligible)
    for (int e = tid; e < VV * 15; e += 256) {
        int i = e / 15, j = e % 15;
        float s = 0.f;
        #pragma unroll
        for (int k = 0; k < 20; k++) s += W1[i * 20 + k] * W2[k * 15 + j];
        t15[e] = s;
    }
    __syncthreads();
    for (int e = tid; e < VV * DD + 32; e += 256) {
        float s = 0.f;
        if (e < VV * DD) {
            int i = e / DD, j = e % DD;
            #pragma unroll
            for (int k = 0; k < 15; k++) s += t15[i * 15 + k] * W3[k * DD + j];
        }
        sWc[e] = s;
    }
    __syncthreads();

    const int warp = tid >> 5, lane = tid & 31;
    const int gw = blockIdx.x * 8 + warp;           // (n,c) row index

    float xm = 0.f;
    if (lane < VV) {
        const float* p = x + (size_t)gw * (TT * VV) + lane;
        float a0 = 0.f, a1 = 0.f, a2 = 0.f, a3 = 0.f;
        float a4 = 0.f, a5 = 0.f, a6 = 0.f, a7 = 0.f;
        #pragma unroll
        for (int t = 0; t < TT; t += 8) {
            a0 += __ldcs(&p[(t + 0) * VV]);
            a1 += __ldcs(&p[(t + 1) * VV]);
            a2 += __ldcs(&p[(t + 2) * VV]);
            a3 += __ldcs(&p[(t + 3) * VV]);
            a4 += __ldcs(&p[(t + 4) * VV]);
            a5 += __ldcs(&p[(t + 5) * VV]);
            a6 += __ldcs(&p[(t + 6) * VV]);
            a7 += __ldcs(&p[(t + 7) * VV]);
        }
        xm = (((a0 + a1) + (a2 + a3)) + ((a4 + a5) + (a6 + a7))) * (1.0f / TT);
    }

    // y[o] = sum_v xm[v] * Wc[v][o]  via warp broadcasts
    float y = 0.f;
    #pragma unroll
    for (int v = 0; v < VV; v++) {
        float xv = __shfl_sync(0xffffffffu, xm, v);
        y += xv * sWc[v * DD + lane];               // lanes >=10 hit pad
    }
    if (lane < DD) g_y[gw * DD + lane] = y;
}

// ---------------------------------------------------------------------------
// Kernel 2: ONE WARP per sample (256 blocks x 32 threads). Zero block
// barriers. One-pass Gram+mean (butterfly-reduced), register-resident
// parallel Jacobi (lane i owns row i, compile-time pair schedule), logeig,
// FC. g_y reads hit L2.
// ---------------------------------------------------------------------------
__global__ void __launch_bounds__(32)
spd_kernel(const float* __restrict__ fcw, const float* __restrict__ fcb,
           float* __restrict__ out) {
    __shared__ float sG [55];
    __shared__ float smn[DD];
    __shared__ float sV [DD * DD];
    __shared__ float sL [FEATD];

    const int n    = blockIdx.x;
    const int lane = threadIdx.x;
    const float* gy = g_y + (size_t)n * CC * DD;

    // one-pass raw Gram + sums; lane handles channels c = lane + 32*i
    float m[DD], g[55];
    #pragma unroll
    for (int j = 0; j < DD; j++) m[j] = 0.f;
    #pragma unroll
    for (int k = 0; k < 55; k++) g[k] = 0.f;
    #pragma unroll
    for (int i = 0; i < 8; i++) {
        const int c = lane + i * 32;
        float yv[DD];
        #pragma unroll
        for (int j = 0; j < DD; j++) yv[j] = gy[c * DD + j];
        #pragma unroll
        for (int j = 0; j < DD; j++) m[j] += yv[j];
        int idx = 0;
        #pragma unroll
        for (int p = 0; p < DD; p++)
            #pragma unroll
            for (int q = p; q < DD; q++) g[idx++] += yv[p] * yv[q];
    }
    #pragma unroll
    for (int j = 0; j < DD; j++) {
        #pragma unroll
        for (int off = 16; off >= 1; off >>= 1)
            m[j] += __shfl_xor_sync(0xffffffffu, m[j], off);
    }
    #pragma unroll
    for (int k = 0; k < 55; k++) {
        #pragma unroll
        for (int off = 16; off >= 1; off >>= 1)
            g[k] += __shfl_xor_sync(0xffffffffu, g[k], off);
    }
    if (lane == 0) {
        #pragma unroll
        for (int k = 0; k < 55; k++) sG[k] = g[k];
        #pragma unroll
        for (int j = 0; j < DD; j++) smn[j] = m[j] * (1.0f / CC);
    }
    __syncwarp();

    // lane i (<10) holds row i of A; V = I. Lanes>=10 clamp to row 0 (inert).
    const int li = (lane < DD) ? lane : 0;
    float Ar[DD], Vr[DD];
    {
        const float mi = smn[li];
        #pragma unroll
        for (int j = 0; j < DD; j++) {
            int p = li < j ? li : j;
            int q = li < j ? j : li;
            int idx = 10 * p - (p * (p - 1)) / 2 + (q - p);
            float cov = (sG[idx] - (float)CC * mi * smn[j]) * (1.0f / (CC - 1));
            Ar[j] = cov + ((li == j) ? 1e-8f : 0.f);
            Vr[j] = (li == j) ? 1.f : 0.f;
        }
    }

    // ---- register Jacobi: 5 sweeps x 9 rounds, compile-time schedule ----
    for (int sweep = 0; sweep < 5; sweep++) {
        #pragma unroll
        for (int r = 0; r < 9; r++) {
            float cc[5], ss[5];
            float cl = 1.f, sl = 0.f;
            int partner = lane;
            #pragma unroll
            for (int k = 0; k < 5; k++) {
                const int i1 = (k == 0) ? 0 : ((r + k - 1) % 9) + 1;
                const int i2 = ((r + 8 - k) % 9) + 1;
                const int p = i1 < i2 ? i1 : i2;
                const int q = i1 < i2 ? i2 : i1;
                float App = __shfl_sync(0xffffffffu, Ar[p], p);
                float Aqq = __shfl_sync(0xffffffffu, Ar[q], q);
                float Apq = __shfl_sync(0xffffffffu, Ar[q], p);
                float c_ = 1.f, s_ = 0.f;
                if (fabsf(Apq) > 1e-20f) {
                    float tau = (Aqq - App) / (2.f * Apq);
                    float tt  = copysignf(1.f, tau) /
                                (fabsf(tau) + sqrtf(1.f + tau * tau));
                    c_ = rsqrtf(1.f + tt * tt);
                    s_ = tt * c_;
                }
                cc[k] = c_; ss[k] = s_;
                if (lane == p) { cl = c_; sl = -s_; partner = q; }
                if (lane == q) { cl = c_; sl =  s_; partner = p; }
            }
            // row phase: A <- J^T A  (exchange full partner row)
            float prow[DD];
            #pragma unroll
            for (int j = 0; j < DD; j++)
                prow[j] = __shfl_sync(0xffffffffu, Ar[j], partner);
            #pragma unroll
            for (int j = 0; j < DD; j++)
                Ar[j] = cl * Ar[j] + sl * prow[j];
            // col phase: A <- A J ; V <- V J (static indices)
            #pragma unroll
            for (int k = 0; k < 5; k++) {
                const int i1 = (k == 0) ? 0 : ((r + k - 1) % 9) + 1;
                const int i2 = ((r + 8 - k) % 9) + 1;
                const int p = i1 < i2 ? i1 : i2;
                const int q = i1 < i2 ? i2 : i1;
                float a = Ar[p], b = Ar[q];
                Ar[p] = cc[k] * a - ss[k] * b;
                Ar[q] = ss[k] * a + cc[k] * b;
                float va = Vr[p], vb = Vr[q];
                Vr[p] = cc[k] * va - ss[k] * vb;
                Vr[q] = ss[k] * va + cc[k] * vb;
            }
        }
    }

    // eigenvalues -> log; logm L = V diag(lw) V^T
    float lw[DD];
    #pragma unroll
    for (int k = 0; k < DD; k++) {
        float lam = __shfl_sync(0xffffffffu, Ar[k], k);
        lw[k] = logf(fmaxf(lam, 1e-12f));
    }
    if (lane < DD) {
        #pragma unroll
        for (int j = 0; j < DD; j++) sV[lane * DD + j] = Vr[j];
    }
    __syncwarp();
    if (lane < DD) {
        #pragma unroll
        for (int j = 0; j < DD; j++) {
            float s = 0.f;
            #pragma unroll
            for (int k = 0; k < DD; k++)
                s += Vr[k] * lw[k] * sV[j * DD + k];
            sL[lane * DD + j] = s;
        }
    }
    __syncwarp();

    // FC: each lane computes outputs m = lane and lane+32
    #pragma unroll
    for (int h = 0; h < 2; h++) {
        const int mo = lane + h * 32;
        float s = fcb[mo];
        const float* wr = fcw + mo * FEATD;
        #pragma unroll 5
        for (int f = 0; f < FEATD; f++) s += sL[f] * wr[f];
        out[n * OUTD + mo] = s;
    }
}

// ---------------------------------------------------------------------------
extern "C" void kernel_launch(void* const* d_in, const int* in_sizes, int n_in,
                              void* d_out, int out_size) {
    const float *x = nullptr, *W1 = nullptr, *W2 = nullptr, *W3 = nullptr;
    const float *fcw = nullptr, *fcb = nullptr;
    for (int i = 0; i < n_in; i++) {
        switch (in_sizes[i]) {
            case NB * CC * TT * VV: x   = (const float*)d_in[i]; break;
            case 500:               W1  = (const float*)d_in[i]; break;
            case 300:               W2  = (const float*)d_in[i]; break;
            case 150:               W3  = (const float*)d_in[i]; break;
            case 6400:              fcw = (const float*)d_in[i]; break;
            case 64:                fcb = (const float*)d_in[i]; break;
            default: break;
        }
    }

    // one warp per (n,c) row: 65536 rows -> 8192 blocks x 8 warps
    meanproj_kernel<<<(NB * CC) / 8, 256>>>(x, W1, W2, W3);

    // one warp per sample
    spd_kernel<<<NB, 32>>>(fcw, fcb, (float*)d_out);
}

// round 5
// speedup vs baseline: 1.1474x; 1.1364x over previous
#include <cuda_runtime.h>
#include <math.h>

#define NB 256      // batch
#define CC 256      // channels
#define TT 64       // time
#define VV 25       // vertices
#define DD 10       // final SPD dim
#define OUTD 64
#define FEATD 100

// scratch (allocation-free rule)
__device__ float g_y[NB * CC * DD];      // projected 10-vectors, 2.6 MB (L2-resident)

// ---------------------------------------------------------------------------
// Kernel 1 (unchanged — at DRAM floor): per (n,c) row: temporal mean then
// project through Wc = W1@W2@W3 -> 10-vector. One warp per row.
// ---------------------------------------------------------------------------
__global__ void __launch_bounds__(256)
meanproj_kernel(const float* __restrict__ x,
                const float* __restrict__ W1,
                const float* __restrict__ W2,
                const float* __restrict__ W3) {
    __shared__ float t15[VV * 15];
    __shared__ float sWc[VV * DD + 32];   // padded so lanes>=10 read safely

    const int tid = threadIdx.x;

    for (int e = tid; e < VV * 15; e += 256) {
        int i = e / 15, j = e % 15;
        float s = 0.f;
        #pragma unroll
        for (int k = 0; k < 20; k++) s += W1[i * 20 + k] * W2[k * 15 + j];
        t15[e] = s;
    }
    __syncthreads();
    for (int e = tid; e < VV * DD + 32; e += 256) {
        float s = 0.f;
        if (e < VV * DD) {
            int i = e / DD, j = e % DD;
            #pragma unroll
            for (int k = 0; k < 15; k++) s += t15[i * 15 + k] * W3[k * DD + j];
        }
        sWc[e] = s;
    }
    __syncthreads();

    const int warp = tid >> 5, lane = tid & 31;
    const int gw = blockIdx.x * 8 + warp;           // (n,c) row index

    float xm = 0.f;
    if (lane < VV) {
        const float* p = x + (size_t)gw * (TT * VV) + lane;
        float a0 = 0.f, a1 = 0.f, a2 = 0.f, a3 = 0.f;
        float a4 = 0.f, a5 = 0.f, a6 = 0.f, a7 = 0.f;
        #pragma unroll
        for (int t = 0; t < TT; t += 8) {
            a0 += __ldcs(&p[(t + 0) * VV]);
            a1 += __ldcs(&p[(t + 1) * VV]);
            a2 += __ldcs(&p[(t + 2) * VV]);
            a3 += __ldcs(&p[(t + 3) * VV]);
            a4 += __ldcs(&p[(t + 4) * VV]);
            a5 += __ldcs(&p[(t + 5) * VV]);
            a6 += __ldcs(&p[(t + 6) * VV]);
            a7 += __ldcs(&p[(t + 7) * VV]);
        }
        xm = (((a0 + a1) + (a2 + a3)) + ((a4 + a5) + (a6 + a7))) * (1.0f / TT);
    }

    float y = 0.f;
    #pragma unroll
    for (int v = 0; v < VV; v++) {
        float xv = __shfl_sync(0xffffffffu, xm, v);
        y += xv * sWc[v * DD + lane];               // lanes >=10 hit pad
    }
    if (lane < DD) g_y[gw * DD + lane] = y;
}

// ---------------------------------------------------------------------------
// Kernel 2: ONE WARP per sample, zero block barriers. Rotation params now use
// MUFU intrinsics (__fdividef / rsqrtf) instead of IEEE div/sqrt sequences;
// 4 Jacobi sweeps.
// ---------------------------------------------------------------------------
__global__ void __launch_bounds__(32)
spd_kernel(const float* __restrict__ fcw, const float* __restrict__ fcb,
           float* __restrict__ out) {
    __shared__ float sG [55];
    __shared__ float smn[DD];
    __shared__ float sV [DD * DD];
    __shared__ float sL [FEATD];

    const int n    = blockIdx.x;
    const int lane = threadIdx.x;
    const float* gy = g_y + (size_t)n * CC * DD;

    // one-pass raw Gram + sums; lane handles channels c = lane + 32*i
    float m[DD], g[55];
    #pragma unroll
    for (int j = 0; j < DD; j++) m[j] = 0.f;
    #pragma unroll
    for (int k = 0; k < 55; k++) g[k] = 0.f;
    #pragma unroll
    for (int i = 0; i < 8; i++) {
        const int c = lane + i * 32;
        float yv[DD];
        #pragma unroll
        for (int j = 0; j < DD; j++) yv[j] = gy[c * DD + j];
        #pragma unroll
        for (int j = 0; j < DD; j++) m[j] += yv[j];
        int idx = 0;
        #pragma unroll
        for (int p = 0; p < DD; p++)
            #pragma unroll
            for (int q = p; q < DD; q++) g[idx++] += yv[p] * yv[q];
    }
    #pragma unroll
    for (int j = 0; j < DD; j++) {
        #pragma unroll
        for (int off = 16; off >= 1; off >>= 1)
            m[j] += __shfl_xor_sync(0xffffffffu, m[j], off);
    }
    #pragma unroll
    for (int k = 0; k < 55; k++) {
        #pragma unroll
        for (int off = 16; off >= 1; off >>= 1)
            g[k] += __shfl_xor_sync(0xffffffffu, g[k], off);
    }
    if (lane == 0) {
        #pragma unroll
        for (int k = 0; k < 55; k++) sG[k] = g[k];
        #pragma unroll
        for (int j = 0; j < DD; j++) smn[j] = m[j] * (1.0f / CC);
    }
    __syncwarp();

    // lane i (<10) holds row i of A; V = I. Lanes>=10 clamp to row 0 (inert).
    const int li = (lane < DD) ? lane : 0;
    float Ar[DD], Vr[DD];
    {
        const float mi = smn[li];
        #pragma unroll
        for (int j = 0; j < DD; j++) {
            int p = li < j ? li : j;
            int q = li < j ? j : li;
            int idx = 10 * p - (p * (p - 1)) / 2 + (q - p);
            float cov = (sG[idx] - (float)CC * mi * smn[j]) * (1.0f / (CC - 1));
            Ar[j] = cov + ((li == j) ? 1e-8f : 0.f);
            Vr[j] = (li == j) ? 1.f : 0.f;
        }
    }

    // ---- register Jacobi: 4 sweeps x 9 rounds, compile-time schedule,
    //      MUFU-based rotation params ----
    for (int sweep = 0; sweep < 4; sweep++) {
        #pragma unroll
        for (int r = 0; r < 9; r++) {
            float cc[5], ss[5];
            float cl = 1.f, sl = 0.f;
            int partner = lane;
            #pragma unroll
            for (int k = 0; k < 5; k++) {
                const int i1 = (k == 0) ? 0 : ((r + k - 1) % 9) + 1;
                const int i2 = ((r + 8 - k) % 9) + 1;
                const int p = i1 < i2 ? i1 : i2;
                const int q = i1 < i2 ? i2 : i1;
                float App = __shfl_sync(0xffffffffu, Ar[p], p);
                float Aqq = __shfl_sync(0xffffffffu, Ar[q], q);
                float Apq = __shfl_sync(0xffffffffu, Ar[q], p);
                float c_ = 1.f, s_ = 0.f;
                if (fabsf(Apq) > 1e-20f) {
                    // tau via MUFU reciprocal-based divide
                    float tau = (Aqq - App) * 0.5f * __fdividef(1.f, Apq);
                    float u   = 1.f + tau * tau;
                    float sq  = u * rsqrtf(u);          // fast sqrt(1+tau^2)
                    float tt  = copysignf(__fdividef(1.f, fabsf(tau) + sq), tau);
                    c_ = rsqrtf(1.f + tt * tt);
                    s_ = tt * c_;
                }
                cc[k] = c_; ss[k] = s_;
                if (lane == p) { cl = c_; sl = -s_; partner = q; }
                if (lane == q) { cl = c_; sl =  s_; partner = p; }
            }
            // row phase: A <- J^T A  (exchange full partner row)
            float prow[DD];
            #pragma unroll
            for (int j = 0; j < DD; j++)
                prow[j] = __shfl_sync(0xffffffffu, Ar[j], partner);
            #pragma unroll
            for (int j = 0; j < DD; j++)
                Ar[j] = cl * Ar[j] + sl * prow[j];
            // col phase: A <- A J ; V <- V J (static indices)
            #pragma unroll
            for (int k = 0; k < 5; k++) {
                const int i1 = (k == 0) ? 0 : ((r + k - 1) % 9) + 1;
                const int i2 = ((r + 8 - k) % 9) + 1;
                const int p = i1 < i2 ? i1 : i2;
                const int q = i1 < i2 ? i2 : i1;
                float a = Ar[p], b = Ar[q];
                Ar[p] = cc[k] * a - ss[k] * b;
                Ar[q] = ss[k] * a + cc[k] * b;
                float va = Vr[p], vb = Vr[q];
                Vr[p] = cc[k] * va - ss[k] * vb;
                Vr[q] = ss[k] * va + cc[k] * vb;
            }
        }
    }

    // eigenvalues -> log; logm L = V diag(lw) V^T
    float lw[DD];
    #pragma unroll
    for (int k = 0; k < DD; k++) {
        float lam = __shfl_sync(0xffffffffu, Ar[k], k);
        lw[k] = __logf(fmaxf(lam, 1e-12f));
    }
    if (lane < DD) {
        #pragma unroll
        for (int j = 0; j < DD; j++) sV[lane * DD + j] = Vr[j];
    }
    __syncwarp();
    if (lane < DD) {
        #pragma unroll
        for (int j = 0; j < DD; j++) {
            float s = 0.f;
            #pragma unroll
            for (int k = 0; k < DD; k++)
                s += Vr[k] * lw[k] * sV[j * DD + k];
            sL[lane * DD + j] = s;
        }
    }
    __syncwarp();

    // FC: each lane computes outputs m = lane and lane+32
    #pragma unroll
    for (int h = 0; h < 2; h++) {
        const int mo = lane + h * 32;
        float s = fcb[mo];
        const float* wr = fcw + mo * FEATD;
        #pragma unroll 5
        for (int f = 0; f < FEATD; f++) s += sL[f] * wr[f];
        out[n * OUTD + mo] = s;
    }
}

// ---------------------------------------------------------------------------
extern "C" void kernel_launch(void* const* d_in, const int* in_sizes, int n_in,
                              void* d_out, int out_size) {
    const float *x = nullptr, *W1 = nullptr, *W2 = nullptr, *W3 = nullptr;
    const float *fcw = nullptr, *fcb = nullptr;
    for (int i = 0; i < n_in; i++) {
        switch (in_sizes[i]) {
            case NB * CC * TT * VV: x   = (const float*)d_in[i]; break;
            case 500:               W1  = (const float*)d_in[i]; break;
            case 300:               W2  = (const float*)d_in[i]; break;
            case 150:               W3  = (const float*)d_in[i]; break;
            case 6400:              fcw = (const float*)d_in[i]; break;
            case 64:                fcb = (const float*)d_in[i]; break;
            default: break;
        }
    }

    // one warp per (n,c) row: 65536 rows -> 8192 blocks x 8 warps
    meanproj_kernel<<<(NB * CC) / 8, 256>>>(x, W1, W2, W3);

    // one warp per sample
    spd_kernel<<<NB, 32>>>(fcw, fcb, (float*)d_out);
}

// round 6
// speedup vs baseline: 1.3927x; 1.2138x over previous
#include <cuda_runtime.h>
#include <math.h>

#define NB 256      // batch
#define CC 256      // channels
#define TT 64       // time
#define VV 25       // vertices
#define DD 10       // final SPD dim
#define OUTD 64
#define FEATD 100

// scratch (allocation-free rule)
__device__ float g_y[NB * CC * DD];      // projected 10-vectors, 2.6 MB (L2-resident)

// ---------------------------------------------------------------------------
// Kernel 1 (unchanged — at DRAM floor): per (n,c) row: temporal mean then
// project through Wc = W1@W2@W3 -> 10-vector. One warp per row.
// ---------------------------------------------------------------------------
__global__ void __launch_bounds__(256)
meanproj_kernel(const float* __restrict__ x,
                const float* __restrict__ W1,
                const float* __restrict__ W2,
                const float* __restrict__ W3) {
    __shared__ float t15[VV * 15];
    __shared__ float sWc[VV * DD + 32];   // padded so lanes>=10 read safely

    const int tid = threadIdx.x;

    for (int e = tid; e < VV * 15; e += 256) {
        int i = e / 15, j = e % 15;
        float s = 0.f;
        #pragma unroll
        for (int k = 0; k < 20; k++) s += W1[i * 20 + k] * W2[k * 15 + j];
        t15[e] = s;
    }
    __syncthreads();
    for (int e = tid; e < VV * DD + 32; e += 256) {
        float s = 0.f;
        if (e < VV * DD) {
            int i = e / DD, j = e % DD;
            #pragma unroll
            for (int k = 0; k < 15; k++) s += t15[i * 15 + k] * W3[k * DD + j];
        }
        sWc[e] = s;
    }
    __syncthreads();

    const int warp = tid >> 5, lane = tid & 31;
    const int gw = blockIdx.x * 8 + warp;           // (n,c) row index

    float xm = 0.f;
    if (lane < VV) {
        const float* p = x + (size_t)gw * (TT * VV) + lane;
        float a0 = 0.f, a1 = 0.f, a2 = 0.f, a3 = 0.f;
        float a4 = 0.f, a5 = 0.f, a6 = 0.f, a7 = 0.f;
        #pragma unroll
        for (int t = 0; t < TT; t += 8) {
            a0 += __ldcs(&p[(t + 0) * VV]);
            a1 += __ldcs(&p[(t + 1) * VV]);
            a2 += __ldcs(&p[(t + 2) * VV]);
            a3 += __ldcs(&p[(t + 3) * VV]);
            a4 += __ldcs(&p[(t + 4) * VV]);
            a5 += __ldcs(&p[(t + 5) * VV]);
            a6 += __ldcs(&p[(t + 6) * VV]);
            a7 += __ldcs(&p[(t + 7) * VV]);
        }
        xm = (((a0 + a1) + (a2 + a3)) + ((a4 + a5) + (a6 + a7))) * (1.0f / TT);
    }

    float y = 0.f;
    #pragma unroll
    for (int v = 0; v < VV; v++) {
        float xv = __shfl_sync(0xffffffffu, xm, v);
        y += xv * sWc[v * DD + lane];               // lanes >=10 hit pad
    }
    if (lane < DD) g_y[gw * DD + lane] = y;
}

// ---------------------------------------------------------------------------
// Kernel 2: ONE WARP per sample. log(A) via scaled Mercator series:
//   s = tr(A)/10,  E = A/s - I  (spectrum of A/s in ~[0.64,1.44] by MP law),
//   log(A) = log(s) I + sum_{k=1..18} (-1)^{k+1} E^k / k.
// Lane i owns row i of the power P in registers; E in smem (padded rows of
// 16 for float4 broadcast reads). No shuffles, no MUFU in the main loop.
// ---------------------------------------------------------------------------
__global__ void __launch_bounds__(32)
spd_kernel(const float* __restrict__ fcw, const float* __restrict__ fcb,
           float* __restrict__ out) {
    __shared__ float sG [55];
    __shared__ float smn[DD];
    __shared__ float sE [DD * 16];        // row-padded to 16 for float4 reads
    __shared__ float sL [FEATD];

    const int n    = blockIdx.x;
    const int lane = threadIdx.x;
    const float* gy = g_y + (size_t)n * CC * DD;

    // ---- one-pass raw Gram + sums; lane handles channels c = lane + 32*i --
    float m[DD], g[55];
    #pragma unroll
    for (int j = 0; j < DD; j++) m[j] = 0.f;
    #pragma unroll
    for (int k = 0; k < 55; k++) g[k] = 0.f;
    #pragma unroll
    for (int i = 0; i < 8; i++) {
        const int c = lane + i * 32;
        float yv[DD];
        #pragma unroll
        for (int j = 0; j < DD; j++) yv[j] = gy[c * DD + j];
        #pragma unroll
        for (int j = 0; j < DD; j++) m[j] += yv[j];
        int idx = 0;
        #pragma unroll
        for (int p = 0; p < DD; p++)
            #pragma unroll
            for (int q = p; q < DD; q++) g[idx++] += yv[p] * yv[q];
    }
    #pragma unroll
    for (int j = 0; j < DD; j++) {
        #pragma unroll
        for (int off = 16; off >= 1; off >>= 1)
            m[j] += __shfl_xor_sync(0xffffffffu, m[j], off);
    }
    #pragma unroll
    for (int k = 0; k < 55; k++) {
        #pragma unroll
        for (int off = 16; off >= 1; off >>= 1)
            g[k] += __shfl_xor_sync(0xffffffffu, g[k], off);
    }
    if (lane == 0) {
        #pragma unroll
        for (int k = 0; k < 55; k++) sG[k] = g[k];
        #pragma unroll
        for (int j = 0; j < DD; j++) smn[j] = m[j] * (1.0f / CC);
    }
    __syncwarp();

    // ---- s = tr(A)/10 (all lanes redundantly) ----
    float s_tr = 0.f;
    #pragma unroll
    for (int i = 0; i < DD; i++) {
        int idx = 10 * i - (i * (i - 1)) / 2;
        s_tr += sG[idx] - (float)CC * smn[i] * smn[i];
    }
    s_tr = s_tr * (1.0f / (CC - 1)) * 0.1f + 1e-8f;   // includes ridge trace/10
    const float inv_s = __fdividef(1.f, s_tr);
    const float logs  = __logf(s_tr);

    // ---- build E = A/s - I; lane i owns row i ----
    float Prow[DD], acc[DD];
    if (lane < DD) {
        const float mi = smn[lane];
        #pragma unroll
        for (int j = 0; j < DD; j++) {
            int p = lane < j ? lane : j;
            int q = lane < j ? j : lane;
            int idx = 10 * p - (p * (p - 1)) / 2 + (q - p);
            float a = (sG[idx] - (float)CC * mi * smn[j]) * (1.0f / (CC - 1))
                    + ((lane == j) ? 1e-8f : 0.f);
            float e = a * inv_s - ((lane == j) ? 1.f : 0.f);
            sE[lane * 16 + j] = e;
            Prow[j] = e;
            acc[j]  = e;
        }
    }
    __syncwarp();

    // ---- Mercator series: 17 dependent 10x10 matmuls, pure FMA ----
    if (lane < DD) {
        float sign = -1.f;
        #pragma unroll 1
        for (int k = 2; k <= 18; k++) {
            float nP[DD];
            #pragma unroll
            for (int j = 0; j < DD; j++) nP[j] = 0.f;
            #pragma unroll
            for (int t = 0; t < DD; t++) {
                const float pv = Prow[t];
                const float4* er = (const float4*)&sE[t * 16];
                float4 e0 = er[0], e1 = er[1];
                float4 e2 = er[2];
                nP[0] += pv * e0.x; nP[1] += pv * e0.y;
                nP[2] += pv * e0.z; nP[3] += pv * e0.w;
                nP[4] += pv * e1.x; nP[5] += pv * e1.y;
                nP[6] += pv * e1.z; nP[7] += pv * e1.w;
                nP[8] += pv * e2.x; nP[9] += pv * e2.y;
            }
            const float coef = sign * __fdividef(1.f, (float)k);
            #pragma unroll
            for (int j = 0; j < DD; j++) {
                Prow[j] = nP[j];
                acc[j] += coef * nP[j];
            }
            sign = -sign;
        }
        #pragma unroll
        for (int j = 0; j < DD; j++)
            sL[lane * DD + j] = acc[j] + ((lane == j) ? logs : 0.f);
    }
    __syncwarp();

    // ---- FC: each lane computes outputs m = lane and lane+32 ----
    #pragma unroll
    for (int h = 0; h < 2; h++) {
        const int mo = lane + h * 32;
        float s = fcb[mo];
        const float* wr = fcw + mo * FEATD;
        #pragma unroll 5
        for (int f = 0; f < FEATD; f++) s += sL[f] * wr[f];
        out[n * OUTD + mo] = s;
    }
}

// ---------------------------------------------------------------------------
extern "C" void kernel_launch(void* const* d_in, const int* in_sizes, int n_in,
                              void* d_out, int out_size) {
    const float *x = nullptr, *W1 = nullptr, *W2 = nullptr, *W3 = nullptr;
    const float *fcw = nullptr, *fcb = nullptr;
    for (int i = 0; i < n_in; i++) {
        switch (in_sizes[i]) {
            case NB * CC * TT * VV: x   = (const float*)d_in[i]; break;
            case 500:               W1  = (const float*)d_in[i]; break;
            case 300:               W2  = (const float*)d_in[i]; break;
            case 150:               W3  = (const float*)d_in[i]; break;
            case 6400:              fcw = (const float*)d_in[i]; break;
            case 64:                fcb = (const float*)d_in[i]; break;
            default: break;
        }
    }

    // one warp per (n,c) row: 65536 rows -> 8192 blocks x 8 warps
    meanproj_kernel<<<(NB * CC) / 8, 256>>>(x, W1, W2, W3);

    // one warp per sample
    spd_kernel<<<NB, 32>>>(fcw, fcb, (float*)d_out);
}